// round 14
// baseline (speedup 1.0000x reference)
#include <cuda_runtime.h>
#include <cstdint>

#define D 128
#define GT 256          // threads per tensor-GEMM CTA (8 warps)
#define PITCHB 20       // u32 pitch for B tiles (16 data + 4 pad)
#define PITCHA 40       // float pitch for A fp32 tile (32 data + 8 pad)
#define AF_FLOATS (128 * PITCHA)      // 5120 floats
#define BT_U32 (128 * PITCHB)         // 2560 u32
#define STAGE_U32 (AF_FLOATS + 2 * BT_U32)  // 10240 u32 / stage
#define SM_TOTAL3 (2 * STAGE_U32 * 4)       // 81920 B

static const int MAX_NU = 100000;
static const int MAX_NI = 50000;
static const int MAX_E  = 300000;

// fp32 intermediates (h1 only; agg eliminated — gather fused into GEMM)
__device__ float g_h1_u[(size_t)MAX_NU * D];
__device__ float g_h1_i[(size_t)MAX_NI * D];
// Pre-split weights (hi/lo bf16x2 per float pair), K-concat [Wl | Wr+Lw]
__device__ uint32_t g_w_h[4 * 128 * 128], g_w_l[4 * 128 * 128];
// CSR scratch
__device__ int g_cnt_u[MAX_NU];
__device__ int g_cnt_i[MAX_NI];
__device__ int g_rowptr_u[MAX_NU + 1];
__device__ int g_rowptr_i[MAX_NI + 1];
__device__ int g_cursor_u[MAX_NU];
__device__ int g_cursor_i[MAX_NI];
__device__ int g_eidx_u[MAX_E];
__device__ int g_eidx_i[MAX_E];
__device__ int g_bsum_u[256];
__device__ int g_bsum_i[256];

// ---------------------------------------------------------------------------
// Helpers
// ---------------------------------------------------------------------------
__device__ __forceinline__ void split2f(float x, float y, uint32_t& h2, uint32_t& l2) {
    asm("cvt.rn.bf16x2.f32 %0, %1, %2;" : "=r"(h2) : "f"(y), "f"(x));
    float hx = __uint_as_float(h2 << 16);
    float hy = __uint_as_float(h2 & 0xFFFF0000u);
    float lx = x - hx, ly = y - hy;
    asm("cvt.rn.bf16x2.f32 %0, %1, %2;" : "=r"(l2) : "f"(ly), "f"(lx));
}
__device__ __forceinline__ void cp16(void* dst, const void* src) {
    uint32_t d = (uint32_t)__cvta_generic_to_shared(dst);
    asm volatile("cp.async.cg.shared.global [%0], [%1], 16;" :: "r"(d), "l"(src));
}
__device__ __forceinline__ void ldsm4(uint32_t* r, const uint32_t* p) {
    uint32_t a = (uint32_t)__cvta_generic_to_shared(p);
    asm volatile("ldmatrix.sync.aligned.m8n8.x4.shared.b16 {%0,%1,%2,%3}, [%4];"
                 : "=r"(r[0]), "=r"(r[1]), "=r"(r[2]), "=r"(r[3]) : "r"(a));
}
__device__ __forceinline__ void mma_bf16(float* c, const uint32_t* a,
                                         uint32_t b0, uint32_t b1) {
    asm volatile(
        "mma.sync.aligned.m16n8k16.row.col.f32.bf16.bf16.f32 "
        "{%0,%1,%2,%3}, {%4,%5,%6,%7}, {%8,%9}, {%0,%1,%2,%3};"
        : "+f"(c[0]), "+f"(c[1]), "+f"(c[2]), "+f"(c[3])
        : "r"(a[0]), "r"(a[1]), "r"(a[2]), "r"(a[3]), "r"(b0), "r"(b1));
}

// ---------------------------------------------------------------------------
// CSR build (fused U+I kernels; unchanged)
// ---------------------------------------------------------------------------
__global__ void k_zero2(int* __restrict__ a, int na, int* __restrict__ b, int nb) {
    int i = blockIdx.x * blockDim.x + threadIdx.x;
    if (i < na) a[i] = 0;
    else if (i - na < nb) b[i - na] = 0;
}
__global__ void k_count2(const int* __restrict__ d1, int* __restrict__ c1,
                         const int* __restrict__ d2, int* __restrict__ c2, int E) {
    int i = blockIdx.x * blockDim.x + threadIdx.x;
    if (i < E) atomicAdd(&c1[d1[i]], 1);
    else if (i - E < E) atomicAdd(&c2[d2[i - E]], 1);
}
__global__ void k_scan1b(const int* __restrict__ cu, int* __restrict__ ru,
                         int* __restrict__ bsu, int nu, int nbU,
                         const int* __restrict__ ci, int* __restrict__ ri,
                         int* __restrict__ bsi, int ni) {
    __shared__ int s[256];
    const bool isU = (int)blockIdx.x < nbU;
    const int* cnt = isU ? cu : ci;
    int* rowptr    = isU ? ru : ri;
    int* bsum      = isU ? bsu : bsi;
    const int n    = isU ? nu : ni;
    const int bid  = isU ? blockIdx.x : blockIdx.x - nbU;
    const int t = threadIdx.x;
    const int base = bid * 1024 + t * 4;
    int v[4], sum = 0;
#pragma unroll
    for (int j = 0; j < 4; j++) {
        v[j] = (base + j < n) ? cnt[base + j] : 0;
        sum += v[j];
    }
    s[t] = sum;
    __syncthreads();
    for (int off = 1; off < 256; off <<= 1) {
        int x = (t >= off) ? s[t - off] : 0;
        __syncthreads();
        s[t] += x;
        __syncthreads();
    }
    int run = s[t] - sum;
    if (t == 255) bsum[bid] = s[255];
#pragma unroll
    for (int j = 0; j < 4; j++) {
        if (base + j < n) rowptr[base + j] = run;
        run += v[j];
    }
}
__global__ void k_scan2b(int* __restrict__ bsu, int nbu,
                         int* __restrict__ bsi, int nbi) {
    int w = threadIdx.x >> 5, lane = threadIdx.x & 31;
    if (w > 1) return;
    int* bs = w ? bsi : bsu;
    int nb  = w ? nbi : nbu;
    int v[8], s = 0;
#pragma unroll
    for (int j = 0; j < 8; j++) {
        int idx = lane * 8 + j;
        v[j] = (idx < nb) ? bs[idx] : 0;
        s += v[j];
    }
    int run = s;
#pragma unroll
    for (int off = 1; off < 32; off <<= 1) {
        int x = __shfl_up_sync(0xFFFFFFFFu, run, off);
        if (lane >= off) run += x;
    }
    run -= s;
#pragma unroll
    for (int j = 0; j < 8; j++) {
        int idx = lane * 8 + j;
        if (idx < nb) bs[idx] = run;
        run += v[j];
    }
}
__global__ void k_scan3b(int* __restrict__ ru, const int* __restrict__ bsu,
                         int* __restrict__ curu, int nu,
                         int* __restrict__ ri, const int* __restrict__ bsi,
                         int* __restrict__ curi, int ni, int E) {
    int i = blockIdx.x * blockDim.x + threadIdx.x;
    if (i < nu) {
        int v = ru[i] + bsu[i >> 10];
        ru[i] = v;
        curu[i] = v;
        if (i == 0) ru[nu] = E;
    } else if (i - nu < ni) {
        int j = i - nu;
        int v = ri[j] + bsi[j >> 10];
        ri[j] = v;
        curi[j] = v;
        if (j == 0) ri[ni] = E;
    }
}
__global__ void k_fill2(const int* __restrict__ s1, const int* __restrict__ d1,
                        int* __restrict__ cu1, int* __restrict__ e1,
                        const int* __restrict__ s2, const int* __restrict__ d2,
                        int* __restrict__ cu2, int* __restrict__ e2, int E) {
    int i = blockIdx.x * blockDim.x + threadIdx.x;
    if (i < E) {
        int p = atomicAdd(&cu1[d1[i]], 1);
        e1[p] = s1[i];
    } else if (i - E < E) {
        int j = i - E;
        int p = atomicAdd(&cu2[d2[j]], 1);
        e2[p] = s2[j];
    }
}

// ---------------------------------------------------------------------------
// Weight prep (all 4 weight sets in one launch)
// ---------------------------------------------------------------------------
struct WprepArgs {
    const float *Wl[4], *Wr[4], *Lw[4];
    uint32_t *oh, *ol;
};
__global__ void k_wprep_all(WprepArgs A) {
    int w = blockIdx.x >> 6;
    int idx = (blockIdx.x & 63) * 256 + threadIdx.x;
    int n = idx >> 7, kp = idx & 127;
    float x, y;
    if (kp < 64) {
        const float2 v = *(const float2*)(A.Wl[w] + n * 128 + kp * 2);
        x = v.x; y = v.y;
    } else {
        const float2 a = *(const float2*)(A.Wr[w] + n * 128 + (kp - 64) * 2);
        const float2 b = *(const float2*)(A.Lw[w] + n * 128 + (kp - 64) * 2);
        x = a.x + b.x; y = a.y + b.y;
    }
    uint32_t h2, l2;
    split2f(x, y, h2, l2);
    A.oh[w * 16384 + idx] = h2;
    A.ol[w * 16384 + idx] = l2;
}

// ---------------------------------------------------------------------------
// Fused gather+GEMM (bf16 split x3, 2-stage pipe):
//   out[m,:] = act( mean_nbr(feat)@Wl^T + x@(Wr+Lw)^T + (bl+lb) )
// Chunks 0-3: A slice produced by in-kernel CSR gather (2 thr/row, float4,
//             mean fused, STS into stage). Chunks 4-7: A = x rows via cp.async.
// B always pre-split cp.async. CTA 128x128, 8 warps (4x2).
// ---------------------------------------------------------------------------
struct GemmArgs {
    const float *feat, *xf;
    const int *rowptr, *eidx;
    const uint32_t *Wh, *Wlo;
    const float *bl, *lb;
    float* outf;
    int M;
};

__global__ __launch_bounds__(GT, 2) void k_gemm2(GemmArgs Ua, GemmArgs Ia,
                                                 int gbU, int do_relu) {
    extern __shared__ uint32_t sm4[];

    const bool isU = (int)blockIdx.x < gbU;
    const GemmArgs G = isU ? Ua : Ia;
    const int row0 = (isU ? blockIdx.x : blockIdx.x - gbU) * 128;
    const int M = G.M;

    const int tid = threadIdx.x;
    const int wid = tid >> 5;
    const int lane = tid & 31;
    const int g = lane >> 2;
    const int q = lane & 3;
    const int wm = wid & 3;
    const int wn = wid >> 2;
    const int lrow = lane & 15;
    const int lcolsel = (lane >> 4) * 4;

    float acc[2][8][4];
#pragma unroll
    for (int mt = 0; mt < 2; mt++)
#pragma unroll
        for (int nt = 0; nt < 8; nt++)
#pragma unroll
            for (int j = 0; j < 4; j++) acc[mt][nt][j] = 0.f;

    // Stage c into buffer s. Chunks 0-3: gather A + async B. 4-7: async A+B.
    auto issueAB = [&](int c, int s) {
        uint32_t* base = sm4 + s * STAGE_U32;
        float* Af = (float*)base;
        uint32_t* Bh = base + AF_FLOATS;
        uint32_t* Bl = base + AF_FLOATS + BT_U32;
        const int kofW = c * 16;
#pragma unroll
        for (int j = 0; j < 2; j++) {          // B: 512 cp16 x2
            int i = tid + j * GT;
            int r = i >> 2, cc = (i & 3) * 4;
            cp16(Bh + r * PITCHB + cc, G.Wh + r * 128 + kofW + cc);
            cp16(Bl + r * PITCHB + cc, G.Wlo + r * 128 + kofW + cc);
        }
        const int kofA = (c & 3) * 32;
        if (c < 4) {
            // Fused gather: 2 threads per row, 16 cols (4 float4) each.
            const int r = tid >> 1;
            const int half = tid & 1;
            const int gr = row0 + r;
            float4 a0 = make_float4(0.f, 0.f, 0.f, 0.f);
            float4 a1 = a0, a2 = a0, a3 = a0;
            if (gr < M) {
                const int s0 = G.rowptr[gr], s1 = G.rowptr[gr + 1];
                const float* fb = G.feat;
                const int cb = kofA + half * 16;
                for (int e = s0; e < s1; e++) {
                    const float4* p =
                        (const float4*)(fb + (size_t)G.eidx[e] * D + cb);
                    float4 v0 = p[0], v1 = p[1], v2 = p[2], v3 = p[3];
                    a0.x += v0.x; a0.y += v0.y; a0.z += v0.z; a0.w += v0.w;
                    a1.x += v1.x; a1.y += v1.y; a1.z += v1.z; a1.w += v1.w;
                    a2.x += v2.x; a2.y += v2.y; a2.z += v2.z; a2.w += v2.w;
                    a3.x += v3.x; a3.y += v3.y; a3.z += v3.z; a3.w += v3.w;
                }
                const float inv = 1.0f / (float)max(s1 - s0, 1);
                a0.x *= inv; a0.y *= inv; a0.z *= inv; a0.w *= inv;
                a1.x *= inv; a1.y *= inv; a1.z *= inv; a1.w *= inv;
                a2.x *= inv; a2.y *= inv; a2.z *= inv; a2.w *= inv;
                a3.x *= inv; a3.y *= inv; a3.z *= inv; a3.w *= inv;
            }
            float4* dst = (float4*)(Af + r * PITCHA + half * 16);
            dst[0] = a0; dst[1] = a1; dst[2] = a2; dst[3] = a3;
        } else {
            const float* Afg = G.xf;
#pragma unroll
            for (int j = 0; j < 4; j++) {      // A: 1024 cp16
                int i = tid + j * GT;
                int r = i >> 3, cc = (i & 7) * 4;
                int gr = min(row0 + r, M - 1);
                cp16(Af + r * PITCHA + cc, Afg + (size_t)gr * D + kofA + cc);
            }
        }
        asm volatile("cp.async.commit_group;");
    };

    // Prologue: two chunks in flight
    issueAB(0, 0);
    issueAB(1, 1);
    asm volatile("cp.async.wait_group 1;");
    __syncthreads();

    for (int c = 0; c < 8; c++) {
        const int cur = c & 1;
        uint32_t* base = sm4 + cur * STAGE_U32;
        const float2* A2 = (const float2*)base;     // pitch 20 float2
        const uint32_t* Bh = base + AF_FLOATS;
        const uint32_t* Bl = base + AF_FLOATS + BT_U32;

#pragma unroll
        for (int ks = 0; ks < 2; ks++) {
            const int c0 = ks * 8 + q;              // float2 col within row
            uint32_t ah[2][4], al[2][4];
#pragma unroll
            for (int mt = 0; mt < 2; mt++) {
                int rb = wm * 32 + mt * 16;
                float2 v0 = A2[(rb + g) * 20 + c0];
                float2 v1 = A2[(rb + g + 8) * 20 + c0];
                float2 v2 = A2[(rb + g) * 20 + c0 + 4];
                float2 v3 = A2[(rb + g + 8) * 20 + c0 + 4];
                split2f(v0.x, v0.y, ah[mt][0], al[mt][0]);
                split2f(v1.x, v1.y, ah[mt][1], al[mt][1]);
                split2f(v2.x, v2.y, ah[mt][2], al[mt][2]);
                split2f(v3.x, v3.y, ah[mt][3], al[mt][3]);
            }
            const int coff = ks * 8 + lcolsel;
#pragma unroll
            for (int p = 0; p < 4; p++) {
                int br = (wn * 64 + p * 16 + lrow) * PITCHB + coff;
                uint32_t bh[4], blr[4];
                ldsm4(bh, Bh + br);
                ldsm4(blr, Bl + br);
#pragma unroll
                for (int mt = 0; mt < 2; mt++) {
                    float* cc0 = acc[mt][2 * p];
                    float* cc1 = acc[mt][2 * p + 1];
                    mma_bf16(cc0, ah[mt], bh[0], bh[2]);
                    mma_bf16(cc0, ah[mt], blr[0], blr[2]);
                    mma_bf16(cc0, al[mt], bh[0], bh[2]);
                    mma_bf16(cc1, ah[mt], bh[1], bh[3]);
                    mma_bf16(cc1, ah[mt], blr[1], blr[3]);
                    mma_bf16(cc1, al[mt], bh[1], bh[3]);
                }
            }
        }
        __syncthreads();   // done reading stage cur
        if (c + 2 < 8) issueAB(c + 2, cur);
        if (c < 6) {
            asm volatile("cp.async.wait_group 1;");
            __syncthreads();
        } else if (c == 6) {
            asm volatile("cp.async.wait_group 0;");
            __syncthreads();
        }
    }

    // Epilogue: fused double-bias + optional ReLU, fp32 float2 stores
#pragma unroll
    for (int nt = 0; nt < 8; nt++) {
        int col = wn * 64 + nt * 8 + q * 2;
        float b0 = G.bl[col] + G.lb[col];
        float b1 = G.bl[col + 1] + G.lb[col + 1];
#pragma unroll
        for (int mt = 0; mt < 2; mt++) {
            float* a = acc[mt][nt];
#pragma unroll
            for (int hh = 0; hh < 2; hh++) {
                int gr = row0 + wm * 32 + mt * 16 + g + hh * 8;
                if (gr >= M) continue;
                float v0 = a[hh * 2 + 0] + b0;
                float v1 = a[hh * 2 + 1] + b1;
                if (do_relu) { v0 = fmaxf(v0, 0.f); v1 = fmaxf(v1, 0.f); }
                *(float2*)(G.outf + (size_t)gr * D + col) = make_float2(v0, v1);
            }
        }
    }
}

// ---------------------------------------------------------------------------
// Launch
// ---------------------------------------------------------------------------
extern "C" void kernel_launch(void* const* d_in, const int* in_sizes, int n_in,
                              void* d_out, int out_size) {
    const float* x_user = (const float*)d_in[0];
    const float* x_item = (const float*)d_in[1];
    const int* ui_src = (const int*)d_in[2];
    const int* ui_dst = (const int*)d_in[3];
    const int* iu_src = (const int*)d_in[4];
    const int* iu_dst = (const int*)d_in[5];
    const float* W1l_ui = (const float*)d_in[6];
    const float* b1_ui  = (const float*)d_in[7];
    const float* W1r_ui = (const float*)d_in[8];
    const float* W1l_iu = (const float*)d_in[9];
    const float* b1_iu  = (const float*)d_in[10];
    const float* W1r_iu = (const float*)d_in[11];
    const float* L1W_u  = (const float*)d_in[12];
    const float* L1b_u  = (const float*)d_in[13];
    const float* L1W_i  = (const float*)d_in[14];
    const float* L1b_i  = (const float*)d_in[15];
    const float* W2l_ui = (const float*)d_in[16];
    const float* b2_ui  = (const float*)d_in[17];
    const float* W2r_ui = (const float*)d_in[18];
    const float* W2l_iu = (const float*)d_in[19];
    const float* b2_iu  = (const float*)d_in[20];
    const float* W2r_iu = (const float*)d_in[21];
    const float* L2W_u  = (const float*)d_in[22];
    const float* L2b_u  = (const float*)d_in[23];
    const float* L2W_i  = (const float*)d_in[24];
    const float* L2b_i  = (const float*)d_in[25];

    const int N_U = in_sizes[0] / D;
    const int N_I = in_sizes[1] / D;
    const int E   = in_sizes[2];

    float *h1_u, *h1_i;
    uint32_t *w_h, *w_l;
    int *cnt_u, *cnt_i, *rp_u, *rp_i, *cur_u, *cur_i, *eidx_u, *eidx_i;
    int *bsum_u, *bsum_i;
    cudaGetSymbolAddress((void**)&h1_u, g_h1_u);
    cudaGetSymbolAddress((void**)&h1_i, g_h1_i);
    cudaGetSymbolAddress((void**)&w_h, g_w_h);
    cudaGetSymbolAddress((void**)&w_l, g_w_l);
    cudaGetSymbolAddress((void**)&cnt_u, g_cnt_u);
    cudaGetSymbolAddress((void**)&cnt_i, g_cnt_i);
    cudaGetSymbolAddress((void**)&rp_u, g_rowptr_u);
    cudaGetSymbolAddress((void**)&rp_i, g_rowptr_i);
    cudaGetSymbolAddress((void**)&cur_u, g_cursor_u);
    cudaGetSymbolAddress((void**)&cur_i, g_cursor_i);
    cudaGetSymbolAddress((void**)&eidx_u, g_eidx_u);
    cudaGetSymbolAddress((void**)&eidx_i, g_eidx_i);
    cudaGetSymbolAddress((void**)&bsum_u, g_bsum_u);
    cudaGetSymbolAddress((void**)&bsum_i, g_bsum_i);

    float* out_u = (float*)d_out;
    float* out_i = out_u + (size_t)N_U * D;

    cudaFuncSetAttribute(k_gemm2, cudaFuncAttributeMaxDynamicSharedMemorySize,
                         SM_TOTAL3);

    const int nbU = (N_U + 1023) / 1024;
    const int nbI = (N_I + 1023) / 1024;
    const int gbU = (N_U + 127) / 128;
    const int gbI = (N_I + 127) / 128;

    // --- weight prep ---
    WprepArgs wp;
    wp.Wl[0] = W1l_iu; wp.Wr[0] = W1r_iu; wp.Lw[0] = L1W_u;
    wp.Wl[1] = W1l_ui; wp.Wr[1] = W1r_ui; wp.Lw[1] = L1W_i;
    wp.Wl[2] = W2l_iu; wp.Wr[2] = W2r_iu; wp.Lw[2] = L2W_u;
    wp.Wl[3] = W2l_ui; wp.Wr[3] = W2r_ui; wp.Lw[3] = L2W_i;
    wp.oh = w_h; wp.ol = w_l;
    k_wprep_all<<<256, 256>>>(wp);

    // --- CSR build ---
    k_zero2<<<(N_U + N_I + 255) / 256, 256>>>(cnt_u, N_U, cnt_i, N_I);
    k_count2<<<(2 * E + 255) / 256, 256>>>(iu_dst, cnt_u, ui_dst, cnt_i, E);
    k_scan1b<<<nbU + nbI, 256>>>(cnt_u, rp_u, bsum_u, N_U, nbU,
                                 cnt_i, rp_i, bsum_i, N_I);
    k_scan2b<<<1, 64>>>(bsum_u, nbU, bsum_i, nbI);
    k_scan3b<<<(N_U + N_I + 255) / 256, 256>>>(rp_u, bsum_u, cur_u, N_U,
                                               rp_i, bsum_i, cur_i, N_I, E);
    k_fill2<<<(2 * E + 255) / 256, 256>>>(iu_src, iu_dst, cur_u, eidx_u,
                                          ui_src, ui_dst, cur_i, eidx_i, E);

    GemmArgs mu1 = {x_item, x_user, rp_u, eidx_u,
                    w_h + 0 * 16384, w_l + 0 * 16384,
                    b1_iu, L1b_u, h1_u, N_U};
    GemmArgs mi1 = {x_user, x_item, rp_i, eidx_i,
                    w_h + 1 * 16384, w_l + 1 * 16384,
                    b1_ui, L1b_i, h1_i, N_I};
    GemmArgs mu2 = {h1_i, h1_u, rp_u, eidx_u,
                    w_h + 2 * 16384, w_l + 2 * 16384,
                    b2_iu, L2b_u, out_u, N_U};
    GemmArgs mi2 = {h1_u, h1_i, rp_i, eidx_i,
                    w_h + 3 * 16384, w_l + 3 * 16384,
                    b2_ui, L2b_i, out_i, N_I};

    // --- layer 1 (fused gather+GEMM) ---
    k_gemm2<<<gbU + gbI, GT, SM_TOTAL3>>>(mu1, mi1, gbU, 1);
    // --- layer 2 (fused gather+GEMM) ---
    k_gemm2<<<gbU + gbI, GT, SM_TOTAL3>>>(mu2, mi2, gbU, 0);
}

// round 15
// speedup vs baseline: 1.0646x; 1.0646x over previous
#include <cuda_runtime.h>
#include <cstdint>

#define D 128
#define GT 256          // threads per tensor-GEMM CTA (8 warps)
#define TM 64           // rows per GEMM CTA
#define PITCHB 20       // u32 pitch for B tiles (16 data + 4 pad)
#define PITCHA 40       // float pitch for A fp32 tile (32 data + 8 pad)
#define AF_FLOATS (TM * PITCHA)       // 2560 floats
#define BT_U32 (128 * PITCHB)         // 2560 u32
#define STAGE_U32 (AF_FLOATS + 2 * BT_U32)  // 7680 u32 / stage
#define SM_TOTAL4 (2 * STAGE_U32 * 4)       // 61440 B

static const int MAX_NU = 100000;
static const int MAX_NI = 50000;
static const int MAX_E  = 300000;

// fp32 intermediates
__device__ float g_agg_u[(size_t)MAX_NU * D];
__device__ float g_agg_i[(size_t)MAX_NI * D];
__device__ float g_h1_u[(size_t)MAX_NU * D];
__device__ float g_h1_i[(size_t)MAX_NI * D];
// Pre-split weights (hi/lo bf16x2 per float pair), K-concat [Wl | Wr+Lw]
__device__ uint32_t g_w_h[4 * 128 * 128], g_w_l[4 * 128 * 128];
// CSR scratch
__device__ int g_cnt_u[MAX_NU];
__device__ int g_cnt_i[MAX_NI];
__device__ int g_rowptr_u[MAX_NU + 1];
__device__ int g_rowptr_i[MAX_NI + 1];
__device__ int g_cursor_u[MAX_NU];
__device__ int g_cursor_i[MAX_NI];
__device__ int g_eidx_u[MAX_E];
__device__ int g_eidx_i[MAX_E];
__device__ int g_bsum_u[256];
__device__ int g_bsum_i[256];

// ---------------------------------------------------------------------------
// Helpers
// ---------------------------------------------------------------------------
__device__ __forceinline__ void split2f(float x, float y, uint32_t& h2, uint32_t& l2) {
    asm("cvt.rn.bf16x2.f32 %0, %1, %2;" : "=r"(h2) : "f"(y), "f"(x));
    float hx = __uint_as_float(h2 << 16);
    float hy = __uint_as_float(h2 & 0xFFFF0000u);
    float lx = x - hx, ly = y - hy;
    asm("cvt.rn.bf16x2.f32 %0, %1, %2;" : "=r"(l2) : "f"(ly), "f"(lx));
}
__device__ __forceinline__ void cp16(void* dst, const void* src) {
    uint32_t d = (uint32_t)__cvta_generic_to_shared(dst);
    asm volatile("cp.async.cg.shared.global [%0], [%1], 16;" :: "r"(d), "l"(src));
}
__device__ __forceinline__ void ldsm4(uint32_t* r, const uint32_t* p) {
    uint32_t a = (uint32_t)__cvta_generic_to_shared(p);
    asm volatile("ldmatrix.sync.aligned.m8n8.x4.shared.b16 {%0,%1,%2,%3}, [%4];"
                 : "=r"(r[0]), "=r"(r[1]), "=r"(r[2]), "=r"(r[3]) : "r"(a));
}
__device__ __forceinline__ void mma_bf16(float* c, const uint32_t* a,
                                         uint32_t b0, uint32_t b1) {
    asm volatile(
        "mma.sync.aligned.m16n8k16.row.col.f32.bf16.bf16.f32 "
        "{%0,%1,%2,%3}, {%4,%5,%6,%7}, {%8,%9}, {%0,%1,%2,%3};"
        : "+f"(c[0]), "+f"(c[1]), "+f"(c[2]), "+f"(c[3])
        : "r"(a[0]), "r"(a[1]), "r"(a[2]), "r"(a[3]), "r"(b0), "r"(b1));
}

// ---------------------------------------------------------------------------
// CSR build (fused U+I kernels)
// ---------------------------------------------------------------------------
__global__ void k_zero2(int* __restrict__ a, int na, int* __restrict__ b, int nb) {
    int i = blockIdx.x * blockDim.x + threadIdx.x;
    if (i < na) a[i] = 0;
    else if (i - na < nb) b[i - na] = 0;
}
__global__ void k_count2(const int* __restrict__ d1, int* __restrict__ c1,
                         const int* __restrict__ d2, int* __restrict__ c2, int E) {
    int i = blockIdx.x * blockDim.x + threadIdx.x;
    if (i < E) atomicAdd(&c1[d1[i]], 1);
    else if (i - E < E) atomicAdd(&c2[d2[i - E]], 1);
}
__global__ void k_scan1b(const int* __restrict__ cu, int* __restrict__ ru,
                         int* __restrict__ bsu, int nu, int nbU,
                         const int* __restrict__ ci, int* __restrict__ ri,
                         int* __restrict__ bsi, int ni) {
    __shared__ int s[256];
    const bool isU = (int)blockIdx.x < nbU;
    const int* cnt = isU ? cu : ci;
    int* rowptr    = isU ? ru : ri;
    int* bsum      = isU ? bsu : bsi;
    const int n    = isU ? nu : ni;
    const int bid  = isU ? blockIdx.x : blockIdx.x - nbU;
    const int t = threadIdx.x;
    const int base = bid * 1024 + t * 4;
    int v[4], sum = 0;
#pragma unroll
    for (int j = 0; j < 4; j++) {
        v[j] = (base + j < n) ? cnt[base + j] : 0;
        sum += v[j];
    }
    s[t] = sum;
    __syncthreads();
    for (int off = 1; off < 256; off <<= 1) {
        int x = (t >= off) ? s[t - off] : 0;
        __syncthreads();
        s[t] += x;
        __syncthreads();
    }
    int run = s[t] - sum;
    if (t == 255) bsum[bid] = s[255];
#pragma unroll
    for (int j = 0; j < 4; j++) {
        if (base + j < n) rowptr[base + j] = run;
        run += v[j];
    }
}
__global__ void k_scan2b(int* __restrict__ bsu, int nbu,
                         int* __restrict__ bsi, int nbi) {
    int w = threadIdx.x >> 5, lane = threadIdx.x & 31;
    if (w > 1) return;
    int* bs = w ? bsi : bsu;
    int nb  = w ? nbi : nbu;
    int v[8], s = 0;
#pragma unroll
    for (int j = 0; j < 8; j++) {
        int idx = lane * 8 + j;
        v[j] = (idx < nb) ? bs[idx] : 0;
        s += v[j];
    }
    int run = s;
#pragma unroll
    for (int off = 1; off < 32; off <<= 1) {
        int x = __shfl_up_sync(0xFFFFFFFFu, run, off);
        if (lane >= off) run += x;
    }
    run -= s;
#pragma unroll
    for (int j = 0; j < 8; j++) {
        int idx = lane * 8 + j;
        if (idx < nb) bs[idx] = run;
        run += v[j];
    }
}
__global__ void k_scan3b(int* __restrict__ ru, const int* __restrict__ bsu,
                         int* __restrict__ curu, int nu,
                         int* __restrict__ ri, const int* __restrict__ bsi,
                         int* __restrict__ curi, int ni, int E) {
    int i = blockIdx.x * blockDim.x + threadIdx.x;
    if (i < nu) {
        int v = ru[i] + bsu[i >> 10];
        ru[i] = v;
        curu[i] = v;
        if (i == 0) ru[nu] = E;
    } else if (i - nu < ni) {
        int j = i - nu;
        int v = ri[j] + bsi[j >> 10];
        ri[j] = v;
        curi[j] = v;
        if (j == 0) ri[ni] = E;
    }
}
__global__ void k_fill2(const int* __restrict__ s1, const int* __restrict__ d1,
                        int* __restrict__ cu1, int* __restrict__ e1,
                        const int* __restrict__ s2, const int* __restrict__ d2,
                        int* __restrict__ cu2, int* __restrict__ e2, int E) {
    int i = blockIdx.x * blockDim.x + threadIdx.x;
    if (i < E) {
        int p = atomicAdd(&cu1[d1[i]], 1);
        e1[p] = s1[i];
    } else if (i - E < E) {
        int j = i - E;
        int p = atomicAdd(&cu2[d2[j]], 1);
        e2[p] = s2[j];
    }
}

// ---------------------------------------------------------------------------
// Weight prep (all 4 weight sets in one launch)
// ---------------------------------------------------------------------------
struct WprepArgs {
    const float *Wl[4], *Wr[4], *Lw[4];
    uint32_t *oh, *ol;
};
__global__ void k_wprep_all(WprepArgs A) {
    int w = blockIdx.x >> 6;
    int idx = (blockIdx.x & 63) * 256 + threadIdx.x;
    int n = idx >> 7, kp = idx & 127;
    float x, y;
    if (kp < 64) {
        const float2 v = *(const float2*)(A.Wl[w] + n * 128 + kp * 2);
        x = v.x; y = v.y;
    } else {
        const float2 a = *(const float2*)(A.Wr[w] + n * 128 + (kp - 64) * 2);
        const float2 b = *(const float2*)(A.Lw[w] + n * 128 + (kp - 64) * 2);
        x = a.x + b.x; y = a.y + b.y;
    }
    uint32_t h2, l2;
    split2f(x, y, h2, l2);
    A.oh[w * 16384 + idx] = h2;
    A.ol[w * 16384 + idx] = l2;
}

// ---------------------------------------------------------------------------
// Fused U+I gather (fp32): one warp per node, float4 lanes, mean fused.
// ---------------------------------------------------------------------------
struct GatherArgs {
    const float* feat;
    const int *rowptr, *eidx;
    float* agg;
    int N;
};
__global__ void k_gather2(GatherArgs U, GatherArgs I, int gaU) {
    const bool isU = (int)blockIdx.x < gaU;
    const GatherArgs A = isU ? U : I;
    const int bid = isU ? blockIdx.x : blockIdx.x - gaU;
    const int node = bid * 8 + (threadIdx.x >> 5);
    if (node >= A.N) return;
    const int lane = threadIdx.x & 31;
    const int s0 = A.rowptr[node], s1 = A.rowptr[node + 1];
    float4 acc = make_float4(0.f, 0.f, 0.f, 0.f);
#pragma unroll 2
    for (int e = s0; e < s1; e++) {
        const float4 v = ((const float4*)(A.feat + (size_t)A.eidx[e] * D))[lane];
        acc.x += v.x; acc.y += v.y; acc.z += v.z; acc.w += v.w;
    }
    const float inv = 1.0f / (float)max(s1 - s0, 1);
    acc.x *= inv; acc.y *= inv; acc.z *= inv; acc.w *= inv;
    ((float4*)(A.agg + (size_t)node * D))[lane] = acc;
}

// ---------------------------------------------------------------------------
// Fused U+I tensor-core SAGE GEMM (bf16 split x3, 64-row tiles, 3 CTAs/SM):
//   out[m,:] = act( agg@Wl^T + x@(Wr+Lw)^T + (bl+lb) )
// CTA 64x128, 8 warps in 2x4 (warp = 32x32). K = 8 chunks of 32, fully-async
// 2-stage pipe. A fp32 cp.async + fragment-time split; B pre-split ldmatrix.
// ---------------------------------------------------------------------------
struct GemmArgs {
    const float *aggf, *xf;
    const uint32_t *Wh, *Wlo;
    const float *bl, *lb;
    float* outf;
    int M;
};

__global__ __launch_bounds__(GT, 3) void k_gemm2(GemmArgs Ua, GemmArgs Ia,
                                                 int gbU, int do_relu) {
    extern __shared__ uint32_t sm4[];

    const bool isU = (int)blockIdx.x < gbU;
    const GemmArgs G = isU ? Ua : Ia;
    const int row0 = (isU ? blockIdx.x : blockIdx.x - gbU) * TM;
    const int M = G.M;

    const int tid = threadIdx.x;
    const int wid = tid >> 5;
    const int lane = tid & 31;
    const int g = lane >> 2;
    const int q = lane & 3;
    const int wm = wid & 1;       // row group (0..1): rows wm*32..+31
    const int wn = wid >> 1;      // col group (0..3): cols wn*32..+31
    const int lrow = lane & 15;
    const int lcolsel = (lane >> 4) * 4;

    float acc[2][4][4];
#pragma unroll
    for (int mt = 0; mt < 2; mt++)
#pragma unroll
        for (int nt = 0; nt < 4; nt++)
#pragma unroll
            for (int j = 0; j < 4; j++) acc[mt][nt][j] = 0.f;

    auto issueAB = [&](int c, int s) {
        uint32_t* base = sm4 + s * STAGE_U32;
        float* Af = (float*)base;
        uint32_t* Bh = base + AF_FLOATS;
        uint32_t* Bl = base + AF_FLOATS + BT_U32;
        const float* Afg = (c < 4) ? G.aggf : G.xf;
        const int kofA = (c & 3) * 32;
        const int kofW = c * 16;
#pragma unroll
        for (int j = 0; j < 2; j++) {          // A: 512 cp16
            int i = tid + j * GT;
            int r = i >> 3, cc = (i & 7) * 4;
            int gr = min(row0 + r, M - 1);
            cp16(Af + r * PITCHA + cc, Afg + (size_t)gr * D + kofA + cc);
        }
#pragma unroll
        for (int j = 0; j < 2; j++) {          // B: 512 cp16 x2
            int i = tid + j * GT;
            int r = i >> 2, cc = (i & 3) * 4;
            cp16(Bh + r * PITCHB + cc, G.Wh + r * 128 + kofW + cc);
            cp16(Bl + r * PITCHB + cc, G.Wlo + r * 128 + kofW + cc);
        }
        asm volatile("cp.async.commit_group;");
    };

    // Prologue: two chunks in flight
    issueAB(0, 0);
    issueAB(1, 1);
    asm volatile("cp.async.wait_group 1;");
    __syncthreads();

    for (int c = 0; c < 8; c++) {
        const int cur = c & 1;
        uint32_t* base = sm4 + cur * STAGE_U32;
        const float2* A2 = (const float2*)base;     // pitch 20 float2
        const uint32_t* Bh = base + AF_FLOATS;
        const uint32_t* Bl = base + AF_FLOATS + BT_U32;

#pragma unroll
        for (int ks = 0; ks < 2; ks++) {
            const int c0 = ks * 8 + q;              // float2 col within row
            uint32_t ah[2][4], al[2][4];
#pragma unroll
            for (int mt = 0; mt < 2; mt++) {
                int rb = wm * 32 + mt * 16;
                float2 v0 = A2[(rb + g) * 20 + c0];
                float2 v1 = A2[(rb + g + 8) * 20 + c0];
                float2 v2 = A2[(rb + g) * 20 + c0 + 4];
                float2 v3 = A2[(rb + g + 8) * 20 + c0 + 4];
                split2f(v0.x, v0.y, ah[mt][0], al[mt][0]);
                split2f(v1.x, v1.y, ah[mt][1], al[mt][1]);
                split2f(v2.x, v2.y, ah[mt][2], al[mt][2]);
                split2f(v3.x, v3.y, ah[mt][3], al[mt][3]);
            }
            const int coff = ks * 8 + lcolsel;
#pragma unroll
            for (int p = 0; p < 2; p++) {
                int br = (wn * 32 + p * 16 + lrow) * PITCHB + coff;
                uint32_t bh[4], blr[4];
                ldsm4(bh, Bh + br);
                ldsm4(blr, Bl + br);
#pragma unroll
                for (int mt = 0; mt < 2; mt++) {
                    float* cc0 = acc[mt][2 * p];
                    float* cc1 = acc[mt][2 * p + 1];
                    mma_bf16(cc0, ah[mt], bh[0], bh[2]);
                    mma_bf16(cc0, ah[mt], blr[0], blr[2]);
                    mma_bf16(cc0, al[mt], bh[0], bh[2]);
                    mma_bf16(cc1, ah[mt], bh[1], bh[3]);
                    mma_bf16(cc1, ah[mt], blr[1], blr[3]);
                    mma_bf16(cc1, al[mt], bh[1], bh[3]);
                }
            }
        }
        __syncthreads();   // done reading stage cur
        if (c + 2 < 8) issueAB(c + 2, cur);
        if (c < 6) {
            asm volatile("cp.async.wait_group 1;");
            __syncthreads();
        } else if (c == 6) {
            asm volatile("cp.async.wait_group 0;");
            __syncthreads();
        }
    }

    // Epilogue: fused double-bias + optional ReLU, fp32 float2 stores
#pragma unroll
    for (int nt = 0; nt < 4; nt++) {
        int col = wn * 32 + nt * 8 + q * 2;
        float b0 = G.bl[col] + G.lb[col];
        float b1 = G.bl[col + 1] + G.lb[col + 1];
#pragma unroll
        for (int mt = 0; mt < 2; mt++) {
            float* a = acc[mt][nt];
#pragma unroll
            for (int hh = 0; hh < 2; hh++) {
                int gr = row0 + wm * 32 + mt * 16 + g + hh * 8;
                if (gr >= M) continue;
                float v0 = a[hh * 2 + 0] + b0;
                float v1 = a[hh * 2 + 1] + b1;
                if (do_relu) { v0 = fmaxf(v0, 0.f); v1 = fmaxf(v1, 0.f); }
                *(float2*)(G.outf + (size_t)gr * D + col) = make_float2(v0, v1);
            }
        }
    }
}

// ---------------------------------------------------------------------------
// Launch
// ---------------------------------------------------------------------------
extern "C" void kernel_launch(void* const* d_in, const int* in_sizes, int n_in,
                              void* d_out, int out_size) {
    const float* x_user = (const float*)d_in[0];
    const float* x_item = (const float*)d_in[1];
    const int* ui_src = (const int*)d_in[2];
    const int* ui_dst = (const int*)d_in[3];
    const int* iu_src = (const int*)d_in[4];
    const int* iu_dst = (const int*)d_in[5];
    const float* W1l_ui = (const float*)d_in[6];
    const float* b1_ui  = (const float*)d_in[7];
    const float* W1r_ui = (const float*)d_in[8];
    const float* W1l_iu = (const float*)d_in[9];
    const float* b1_iu  = (const float*)d_in[10];
    const float* W1r_iu = (const float*)d_in[11];
    const float* L1W_u  = (const float*)d_in[12];
    const float* L1b_u  = (const float*)d_in[13];
    const float* L1W_i  = (const float*)d_in[14];
    const float* L1b_i  = (const float*)d_in[15];
    const float* W2l_ui = (const float*)d_in[16];
    const float* b2_ui  = (const float*)d_in[17];
    const float* W2r_ui = (const float*)d_in[18];
    const float* W2l_iu = (const float*)d_in[19];
    const float* b2_iu  = (const float*)d_in[20];
    const float* W2r_iu = (const float*)d_in[21];
    const float* L2W_u  = (const float*)d_in[22];
    const float* L2b_u  = (const float*)d_in[23];
    const float* L2W_i  = (const float*)d_in[24];
    const float* L2b_i  = (const float*)d_in[25];

    const int N_U = in_sizes[0] / D;
    const int N_I = in_sizes[1] / D;
    const int E   = in_sizes[2];

    float *agg_u, *agg_i, *h1_u, *h1_i;
    uint32_t *w_h, *w_l;
    int *cnt_u, *cnt_i, *rp_u, *rp_i, *cur_u, *cur_i, *eidx_u, *eidx_i;
    int *bsum_u, *bsum_i;
    cudaGetSymbolAddress((void**)&agg_u, g_agg_u);
    cudaGetSymbolAddress((void**)&agg_i, g_agg_i);
    cudaGetSymbolAddress((void**)&h1_u, g_h1_u);
    cudaGetSymbolAddress((void**)&h1_i, g_h1_i);
    cudaGetSymbolAddress((void**)&w_h, g_w_h);
    cudaGetSymbolAddress((void**)&w_l, g_w_l);
    cudaGetSymbolAddress((void**)&cnt_u, g_cnt_u);
    cudaGetSymbolAddress((void**)&cnt_i, g_cnt_i);
    cudaGetSymbolAddress((void**)&rp_u, g_rowptr_u);
    cudaGetSymbolAddress((void**)&rp_i, g_rowptr_i);
    cudaGetSymbolAddress((void**)&cur_u, g_cursor_u);
    cudaGetSymbolAddress((void**)&cur_i, g_cursor_i);
    cudaGetSymbolAddress((void**)&eidx_u, g_eidx_u);
    cudaGetSymbolAddress((void**)&eidx_i, g_eidx_i);
    cudaGetSymbolAddress((void**)&bsum_u, g_bsum_u);
    cudaGetSymbolAddress((void**)&bsum_i, g_bsum_i);

    float* out_u = (float*)d_out;
    float* out_i = out_u + (size_t)N_U * D;

    cudaFuncSetAttribute(k_gemm2, cudaFuncAttributeMaxDynamicSharedMemorySize,
                         SM_TOTAL4);

    const int nbU = (N_U + 1023) / 1024;
    const int nbI = (N_I + 1023) / 1024;
    const int gaU = (N_U + 7) / 8;
    const int gaI = (N_I + 7) / 8;
    const int gbU = (N_U + TM - 1) / TM;
    const int gbI = (N_I + TM - 1) / TM;

    // --- weight prep ---
    WprepArgs wp;
    wp.Wl[0] = W1l_iu; wp.Wr[0] = W1r_iu; wp.Lw[0] = L1W_u;
    wp.Wl[1] = W1l_ui; wp.Wr[1] = W1r_ui; wp.Lw[1] = L1W_i;
    wp.Wl[2] = W2l_iu; wp.Wr[2] = W2r_iu; wp.Lw[2] = L2W_u;
    wp.Wl[3] = W2l_ui; wp.Wr[3] = W2r_ui; wp.Lw[3] = L2W_i;
    wp.oh = w_h; wp.ol = w_l;
    k_wprep_all<<<256, 256>>>(wp);

    // --- CSR build ---
    k_zero2<<<(N_U + N_I + 255) / 256, 256>>>(cnt_u, N_U, cnt_i, N_I);
    k_count2<<<(2 * E + 255) / 256, 256>>>(iu_dst, cnt_u, ui_dst, cnt_i, E);
    k_scan1b<<<nbU + nbI, 256>>>(cnt_u, rp_u, bsum_u, N_U, nbU,
                                 cnt_i, rp_i, bsum_i, N_I);
    k_scan2b<<<1, 64>>>(bsum_u, nbU, bsum_i, nbI);
    k_scan3b<<<(N_U + N_I + 255) / 256, 256>>>(rp_u, bsum_u, cur_u, N_U,
                                               rp_i, bsum_i, cur_i, N_I, E);
    k_fill2<<<(2 * E + 255) / 256, 256>>>(iu_src, iu_dst, cur_u, eidx_u,
                                          ui_src, ui_dst, cur_i, eidx_i, E);

    GatherArgs gu1 = {x_item, rp_u, eidx_u, agg_u, N_U};
    GatherArgs gi1 = {x_user, rp_i, eidx_i, agg_i, N_I};
    GatherArgs gu2 = {h1_i, rp_u, eidx_u, agg_u, N_U};
    GatherArgs gi2 = {h1_u, rp_i, eidx_i, agg_i, N_I};
    GemmArgs mu1 = {agg_u, x_user, w_h + 0 * 16384, w_l + 0 * 16384,
                    b1_iu, L1b_u, h1_u, N_U};
    GemmArgs mi1 = {agg_i, x_item, w_h + 1 * 16384, w_l + 1 * 16384,
                    b1_ui, L1b_i, h1_i, N_I};
    GemmArgs mu2 = {agg_u, h1_u, w_h + 2 * 16384, w_l + 2 * 16384,
                    b2_iu, L2b_u, out_u, N_U};
    GemmArgs mi2 = {agg_i, h1_i, w_h + 3 * 16384, w_l + 3 * 16384,
                    b2_ui, L2b_i, out_i, N_I};

    // --- layer 1 ---
    k_gather2<<<gaU + gaI, 256>>>(gu1, gi1, gaU);
    k_gemm2<<<gbU + gbI, GT, SM_TOTAL4>>>(mu1, mi1, gbU, 1);
    // --- layer 2 ---
    k_gather2<<<gaU + gaI, 256>>>(gu2, gi2, gaU);
    k_gemm2<<<gbU + gbI, GT, SM_TOTAL4>>>(mu2, mi2, gbU, 0);
}

// round 16
// speedup vs baseline: 1.2252x; 1.1509x over previous
#include <cuda_runtime.h>
#include <cstdint>

#define D 128
#define GT 256          // threads per tensor-GEMM CTA (8 warps)
#define PITCH2 20       // u32 pitch per smem tile row (16 data + 4 pad)
#define TU (128 * PITCH2)

static const int MAX_NU = 100000;
static const int MAX_NI = 50000;
static const int MAX_E  = 300000;

// fp32 intermediates
__device__ float g_agg_u[(size_t)MAX_NU * D];
__device__ float g_agg_i[(size_t)MAX_NI * D];
__device__ float g_h1_u[(size_t)MAX_NU * D];
__device__ float g_h1_i[(size_t)MAX_NI * D];
// Pre-split weights (hi/lo bf16x2 per float pair), K-concat [Wl | Wr+Lw]
__device__ uint32_t g_w_h[4 * 128 * 128], g_w_l[4 * 128 * 128];
// CSR scratch
__device__ int g_cnt_u[MAX_NU];
__device__ int g_cnt_i[MAX_NI];
__device__ int g_rowptr_u[MAX_NU + 1];
__device__ int g_rowptr_i[MAX_NI + 1];
__device__ int g_cursor_u[MAX_NU];
__device__ int g_cursor_i[MAX_NI];
__device__ int g_eidx_u[MAX_E];
__device__ int g_eidx_i[MAX_E];
__device__ int g_bsum_u[256];
__device__ int g_bsum_i[256];

// ---------------------------------------------------------------------------
// Helpers
// ---------------------------------------------------------------------------
__device__ __forceinline__ void split2f(float x, float y, uint32_t& h2, uint32_t& l2) {
    asm("cvt.rn.bf16x2.f32 %0, %1, %2;" : "=r"(h2) : "f"(y), "f"(x));
    float hx = __uint_as_float(h2 << 16);
    float hy = __uint_as_float(h2 & 0xFFFF0000u);
    float lx = x - hx, ly = y - hy;
    asm("cvt.rn.bf16x2.f32 %0, %1, %2;" : "=r"(l2) : "f"(ly), "f"(lx));
}
__device__ __forceinline__ void cp16(void* dst, const void* src) {
    uint32_t d = (uint32_t)__cvta_generic_to_shared(dst);
    asm volatile("cp.async.cg.shared.global [%0], [%1], 16;" :: "r"(d), "l"(src));
}
__device__ __forceinline__ void ldsm4(uint32_t* r, const uint32_t* p) {
    uint32_t a = (uint32_t)__cvta_generic_to_shared(p);
    asm volatile("ldmatrix.sync.aligned.m8n8.x4.shared.b16 {%0,%1,%2,%3}, [%4];"
                 : "=r"(r[0]), "=r"(r[1]), "=r"(r[2]), "=r"(r[3]) : "r"(a));
}
__device__ __forceinline__ void mma_bf16(float* c, const uint32_t* a,
                                         uint32_t b0, uint32_t b1) {
    asm volatile(
        "mma.sync.aligned.m16n8k16.row.col.f32.bf16.bf16.f32 "
        "{%0,%1,%2,%3}, {%4,%5,%6,%7}, {%8,%9}, {%0,%1,%2,%3};"
        : "+f"(c[0]), "+f"(c[1]), "+f"(c[2]), "+f"(c[3])
        : "r"(a[0]), "r"(a[1]), "r"(a[2]), "r"(a[3]), "r"(b0), "r"(b1));
}

// ---------------------------------------------------------------------------
// CSR build (fused U+I kernels)
// ---------------------------------------------------------------------------
__global__ void k_count2(const int* __restrict__ d1, int* __restrict__ c1,
                         const int* __restrict__ d2, int* __restrict__ c2, int E) {
    int i = blockIdx.x * blockDim.x + threadIdx.x;
    if (i < E) atomicAdd(&c1[d1[i]], 1);
    else if (i - E < E) atomicAdd(&c2[d2[i - E]], 1);
}
__global__ void k_scan1b(const int* __restrict__ cu, int* __restrict__ ru,
                         int* __restrict__ bsu, int nu, int nbU,
                         const int* __restrict__ ci, int* __restrict__ ri,
                         int* __restrict__ bsi, int ni) {
    __shared__ int s[256];
    const bool isU = (int)blockIdx.x < nbU;
    const int* cnt = isU ? cu : ci;
    int* rowptr    = isU ? ru : ri;
    int* bsum      = isU ? bsu : bsi;
    const int n    = isU ? nu : ni;
    const int bid  = isU ? blockIdx.x : blockIdx.x - nbU;
    const int t = threadIdx.x;
    const int base = bid * 1024 + t * 4;
    int v[4], sum = 0;
#pragma unroll
    for (int j = 0; j < 4; j++) {
        v[j] = (base + j < n) ? cnt[base + j] : 0;
        sum += v[j];
    }
    s[t] = sum;
    __syncthreads();
    for (int off = 1; off < 256; off <<= 1) {
        int x = (t >= off) ? s[t - off] : 0;
        __syncthreads();
        s[t] += x;
        __syncthreads();
    }
    int run = s[t] - sum;
    if (t == 255) bsum[bid] = s[255];
#pragma unroll
    for (int j = 0; j < 4; j++) {
        if (base + j < n) rowptr[base + j] = run;
        run += v[j];
    }
}
__global__ void k_scan2b(int* __restrict__ bsu, int nbu,
                         int* __restrict__ bsi, int nbi) {
    int w = threadIdx.x >> 5, lane = threadIdx.x & 31;
    if (w > 1) return;
    int* bs = w ? bsi : bsu;
    int nb  = w ? nbi : nbu;
    int v[8], s = 0;
#pragma unroll
    for (int j = 0; j < 8; j++) {
        int idx = lane * 8 + j;
        v[j] = (idx < nb) ? bs[idx] : 0;
        s += v[j];
    }
    int run = s;
#pragma unroll
    for (int off = 1; off < 32; off <<= 1) {
        int x = __shfl_up_sync(0xFFFFFFFFu, run, off);
        if (lane >= off) run += x;
    }
    run -= s;
#pragma unroll
    for (int j = 0; j < 8; j++) {
        int idx = lane * 8 + j;
        if (idx < nb) bs[idx] = run;
        run += v[j];
    }
}
__global__ void k_scan3b(int* __restrict__ ru, const int* __restrict__ bsu,
                         int* __restrict__ curu, int nu,
                         int* __restrict__ ri, const int* __restrict__ bsi,
                         int* __restrict__ curi, int ni, int E) {
    int i = blockIdx.x * blockDim.x + threadIdx.x;
    if (i < nu) {
        int v = ru[i] + bsu[i >> 10];
        ru[i] = v;
        curu[i] = v;
        if (i == 0) ru[nu] = E;
    } else if (i - nu < ni) {
        int j = i - nu;
        int v = ri[j] + bsi[j >> 10];
        ri[j] = v;
        curi[j] = v;
        if (j == 0) ri[ni] = E;
    }
}
__global__ void k_fill2(const int* __restrict__ s1, const int* __restrict__ d1,
                        int* __restrict__ cu1, int* __restrict__ e1,
                        const int* __restrict__ s2, const int* __restrict__ d2,
                        int* __restrict__ cu2, int* __restrict__ e2, int E) {
    int i = blockIdx.x * blockDim.x + threadIdx.x;
    if (i < E) {
        int p = atomicAdd(&cu1[d1[i]], 1);
        e1[p] = s1[i];
    } else if (i - E < E) {
        int j = i - E;
        int p = atomicAdd(&cu2[d2[j]], 1);
        e2[p] = s2[j];
    }
}

// ---------------------------------------------------------------------------
// Weight prep (all 4 sets) + fused zeroing of degree counters
// ---------------------------------------------------------------------------
struct WprepArgs {
    const float *Wl[4], *Wr[4], *Lw[4];
    uint32_t *oh, *ol;
    int *cnt_u, *cnt_i;
    int N_U, N_I;
};
__global__ void k_wprep_all(WprepArgs A) {
    const int gid = blockIdx.x * 256 + threadIdx.x;
    const int gsz = gridDim.x * 256;
    // zero degree counters (grid-stride; folds the old k_zero2 launch)
    for (int i = gid; i < A.N_U; i += gsz) A.cnt_u[i] = 0;
    for (int i = gid; i < A.N_I; i += gsz) A.cnt_i[i] = 0;
    // weight split
    int w = blockIdx.x >> 6;
    int idx = (blockIdx.x & 63) * 256 + threadIdx.x;
    int n = idx >> 7, kp = idx & 127;
    float x, y;
    if (kp < 64) {
        const float2 v = *(const float2*)(A.Wl[w] + n * 128 + kp * 2);
        x = v.x; y = v.y;
    } else {
        const float2 a = *(const float2*)(A.Wr[w] + n * 128 + (kp - 64) * 2);
        const float2 b = *(const float2*)(A.Lw[w] + n * 128 + (kp - 64) * 2);
        x = a.x + b.x; y = a.y + b.y;
    }
    uint32_t h2, l2;
    split2f(x, y, h2, l2);
    A.oh[w * 16384 + idx] = h2;
    A.ol[w * 16384 + idx] = l2;
}

// ---------------------------------------------------------------------------
// Fused U+I gather (fp32): one warp per node, float4 lanes, mean fused.
// ---------------------------------------------------------------------------
struct GatherArgs {
    const float* feat;
    const int *rowptr, *eidx;
    float* agg;
    int N;
};
__global__ void k_gather2(GatherArgs U, GatherArgs I, int gaU) {
    const bool isU = (int)blockIdx.x < gaU;
    const GatherArgs A = isU ? U : I;
    const int bid = isU ? blockIdx.x : blockIdx.x - gaU;
    const int node = bid * 8 + (threadIdx.x >> 5);
    if (node >= A.N) return;
    const int lane = threadIdx.x & 31;
    const int s0 = A.rowptr[node], s1 = A.rowptr[node + 1];
    float4 acc = make_float4(0.f, 0.f, 0.f, 0.f);
#pragma unroll 2
    for (int e = s0; e < s1; e++) {
        const float4 v = ((const float4*)(A.feat + (size_t)A.eidx[e] * D))[lane];
        acc.x += v.x; acc.y += v.y; acc.z += v.z; acc.w += v.w;
    }
    const float inv = 1.0f / (float)max(s1 - s0, 1);
    acc.x *= inv; acc.y *= inv; acc.z *= inv; acc.w *= inv;
    ((float4*)(A.agg + (size_t)node * D))[lane] = acc;
}

// ---------------------------------------------------------------------------
// Fused U+I tensor-core SAGE GEMM (bf16 split x3, 2-stage pipelined, with
// pass-interleaved MMA ordering — same-accumulator spacing 4):
//   out[m,:] = act( agg@Wl^T + x@(Wr+Lw)^T + (bl+lb) )
// K = 8 chunks of 32, double-buffered A (LDG->reg prefetch->split->STS)
// and B (pre-split cp.async). CTA 128x128, 8 warps (4x2).
// ---------------------------------------------------------------------------
struct GemmArgs {
    const float *aggf, *xf;
    const uint32_t *Wh, *Wlo;
    const float *bl, *lb;
    float* outf;
    int M;
};

#define SM_TOTAL2 (2 * 4 * TU * 4)   // 2 stages x 4 tiles x TU u32 x 4B

__global__ __launch_bounds__(GT, 2) void k_gemm2(GemmArgs Ua, GemmArgs Ia,
                                                 int gbU, int do_relu) {
    extern __shared__ uint32_t sm4[];

    const bool isU = (int)blockIdx.x < gbU;
    const GemmArgs G = isU ? Ua : Ia;
    const int row0 = (isU ? blockIdx.x : blockIdx.x - gbU) * 128;
    const int M = G.M;

    const int tid = threadIdx.x;
    const int wid = tid >> 5;
    const int lane = tid & 31;
    const int g = lane >> 2;
    const int q = lane & 3;
    const int wm = wid & 3;
    const int wn = wid >> 2;
    const int lrow = lane & 15;
    const int lcolsel = (lane >> 4) * 4;

    float4 pf[4];

    float acc[2][8][4];
#pragma unroll
    for (int mt = 0; mt < 2; mt++)
#pragma unroll
        for (int nt = 0; nt < 8; nt++)
#pragma unroll
            for (int j = 0; j < 4; j++) acc[mt][nt][j] = 0.f;

    auto stg = [&](int s) { return sm4 + s * 4 * TU; };

    auto issueB = [&](int c, int s) {
        const int kofW = c * 16;
        uint32_t* Bh = stg(s) + 2 * TU;
        uint32_t* Bl = stg(s) + 3 * TU;
#pragma unroll
        for (int j = 0; j < 2; j++) {
            int i = tid + j * GT;
            int r = i >> 2, c4 = (i & 3) * 4;
            int toff = r * PITCH2 + c4;
            cp16(Bh + toff, G.Wh + r * 128 + kofW + c4);
            cp16(Bl + toff, G.Wlo + r * 128 + kofW + c4);
        }
        asm volatile("cp.async.commit_group;");
    };
    auto loadA = [&](int c) {
        const float* Af = (c < 4) ? G.aggf : G.xf;
        const int kofA = (c & 3) * 32;
#pragma unroll
        for (int j = 0; j < 4; j++) {
            int i = tid + j * GT;
            int r = i >> 3, c4 = i & 7;
            int gr = row0 + r;
            pf[j] = (gr < M)
                ? *(const float4*)(Af + (size_t)gr * D + kofA + c4 * 4)
                : make_float4(0.f, 0.f, 0.f, 0.f);
        }
    };
    auto storeA = [&](int s) {
        uint32_t* Ah = stg(s);
        uint32_t* Al = stg(s) + TU;
#pragma unroll
        for (int j = 0; j < 4; j++) {
            int i = tid + j * GT;
            int r = i >> 3, c4 = i & 7;
            uint32_t h0, l0, h1, l1;
            split2f(pf[j].x, pf[j].y, h0, l0);
            split2f(pf[j].z, pf[j].w, h1, l1);
            int toff = r * PITCH2 + c4 * 2;
            Ah[toff] = h0; Ah[toff + 1] = h1;
            Al[toff] = l0; Al[toff + 1] = l1;
        }
    };

    // Prologue: fill stage 0 with chunk 0
    issueB(0, 0);
    loadA(0);
    storeA(0);
    asm volatile("cp.async.wait_group 0;");
    __syncthreads();

    for (int c = 0; c < 8; c++) {
        const int cur = c & 1, nxt = cur ^ 1;
        if (c < 7) {
            issueB(c + 1, nxt);
            loadA(c + 1);
        }
        const uint32_t* Ah = stg(cur);
        const uint32_t* Al = stg(cur) + TU;
        const uint32_t* Bh = stg(cur) + 2 * TU;
        const uint32_t* Bl = stg(cur) + 3 * TU;
#pragma unroll
        for (int ks = 0; ks < 2; ks++) {
            const int coff = ks * 8 + lcolsel;
            uint32_t ah[2][4], al[2][4];
#pragma unroll
            for (int mt = 0; mt < 2; mt++) {
                int ar = (wm * 32 + mt * 16 + lrow) * PITCH2 + coff;
                ldsm4(ah[mt], Ah + ar);
                ldsm4(al[mt], Al + ar);
            }
#pragma unroll
            for (int p = 0; p < 4; p++) {
                int br = (wn * 64 + p * 16 + lrow) * PITCH2 + coff;
                uint32_t bh[4], blr[4];
                ldsm4(bh, Bh + br);
                ldsm4(blr, Bl + br);
                float* c00 = acc[0][2 * p];
                float* c10 = acc[0][2 * p + 1];
                float* c01 = acc[1][2 * p];
                float* c11 = acc[1][2 * p + 1];
                // pass hh: 4 independent accumulators
                mma_bf16(c00, ah[0], bh[0], bh[2]);
                mma_bf16(c10, ah[0], bh[1], bh[3]);
                mma_bf16(c01, ah[1], bh[0], bh[2]);
                mma_bf16(c11, ah[1], bh[1], bh[3]);
                // pass hl
                mma_bf16(c00, ah[0], blr[0], blr[2]);
                mma_bf16(c10, ah[0], blr[1], blr[3]);
                mma_bf16(c01, ah[1], blr[0], blr[2]);
                mma_bf16(c11, ah[1], blr[1], blr[3]);
                // pass lh
                mma_bf16(c00, al[0], bh[0], bh[2]);
                mma_bf16(c10, al[0], bh[1], bh[3]);
                mma_bf16(c01, al[1], bh[0], bh[2]);
                mma_bf16(c11, al[1], bh[1], bh[3]);
            }
        }
        if (c < 7) {
            storeA(nxt);
            asm volatile("cp.async.wait_group 0;");
        }
        __syncthreads();
    }

    // Epilogue: fused double-bias + optional ReLU, fp32 float2 stores
#pragma unroll
    for (int nt = 0; nt < 8; nt++) {
        int col = wn * 64 + nt * 8 + q * 2;
        float b0 = G.bl[col] + G.lb[col];
        float b1 = G.bl[col + 1] + G.lb[col + 1];
#pragma unroll
        for (int mt = 0; mt < 2; mt++) {
            float* a = acc[mt][nt];
#pragma unroll
            for (int hh = 0; hh < 2; hh++) {
                int gr = row0 + wm * 32 + mt * 16 + g + hh * 8;
                if (gr >= M) continue;
                float v0 = a[hh * 2 + 0] + b0;
                float v1 = a[hh * 2 + 1] + b1;
                if (do_relu) { v0 = fmaxf(v0, 0.f); v1 = fmaxf(v1, 0.f); }
                *(float2*)(G.outf + (size_t)gr * D + col) = make_float2(v0, v1);
            }
        }
    }
}

// ---------------------------------------------------------------------------
// Launch
// ---------------------------------------------------------------------------
extern "C" void kernel_launch(void* const* d_in, const int* in_sizes, int n_in,
                              void* d_out, int out_size) {
    const float* x_user = (const float*)d_in[0];
    const float* x_item = (const float*)d_in[1];
    const int* ui_src = (const int*)d_in[2];
    const int* ui_dst = (const int*)d_in[3];
    const int* iu_src = (const int*)d_in[4];
    const int* iu_dst = (const int*)d_in[5];
    const float* W1l_ui = (const float*)d_in[6];
    const float* b1_ui  = (const float*)d_in[7];
    const float* W1r_ui = (const float*)d_in[8];
    const float* W1l_iu = (const float*)d_in[9];
    const float* b1_iu  = (const float*)d_in[10];
    const float* W1r_iu = (const float*)d_in[11];
    const float* L1W_u  = (const float*)d_in[12];
    const float* L1b_u  = (const float*)d_in[13];
    const float* L1W_i  = (const float*)d_in[14];
    const float* L1b_i  = (const float*)d_in[15];
    const float* W2l_ui = (const float*)d_in[16];
    const float* b2_ui  = (const float*)d_in[17];
    const float* W2r_ui = (const float*)d_in[18];
    const float* W2l_iu = (const float*)d_in[19];
    const float* b2_iu  = (const float*)d_in[20];
    const float* W2r_iu = (const float*)d_in[21];
    const float* L2W_u  = (const float*)d_in[22];
    const float* L2b_u  = (const float*)d_in[23];
    const float* L2W_i  = (const float*)d_in[24];
    const float* L2b_i  = (const float*)d_in[25];

    const int N_U = in_sizes[0] / D;
    const int N_I = in_sizes[1] / D;
    const int E   = in_sizes[2];

    float *agg_u, *agg_i, *h1_u, *h1_i;
    uint32_t *w_h, *w_l;
    int *cnt_u, *cnt_i, *rp_u, *rp_i, *cur_u, *cur_i, *eidx_u, *eidx_i;
    int *bsum_u, *bsum_i;
    cudaGetSymbolAddress((void**)&agg_u, g_agg_u);
    cudaGetSymbolAddress((void**)&agg_i, g_agg_i);
    cudaGetSymbolAddress((void**)&h1_u, g_h1_u);
    cudaGetSymbolAddress((void**)&h1_i, g_h1_i);
    cudaGetSymbolAddress((void**)&w_h, g_w_h);
    cudaGetSymbolAddress((void**)&w_l, g_w_l);
    cudaGetSymbolAddress((void**)&cnt_u, g_cnt_u);
    cudaGetSymbolAddress((void**)&cnt_i, g_cnt_i);
    cudaGetSymbolAddress((void**)&rp_u, g_rowptr_u);
    cudaGetSymbolAddress((void**)&rp_i, g_rowptr_i);
    cudaGetSymbolAddress((void**)&cur_u, g_cursor_u);
    cudaGetSymbolAddress((void**)&cur_i, g_cursor_i);
    cudaGetSymbolAddress((void**)&eidx_u, g_eidx_u);
    cudaGetSymbolAddress((void**)&eidx_i, g_eidx_i);
    cudaGetSymbolAddress((void**)&bsum_u, g_bsum_u);
    cudaGetSymbolAddress((void**)&bsum_i, g_bsum_i);

    float* out_u = (float*)d_out;
    float* out_i = out_u + (size_t)N_U * D;

    cudaFuncSetAttribute(k_gemm2, cudaFuncAttributeMaxDynamicSharedMemorySize,
                         SM_TOTAL2);

    const int nbU = (N_U + 1023) / 1024;
    const int nbI = (N_I + 1023) / 1024;
    const int gaU = (N_U + 7) / 8;
    const int gaI = (N_I + 7) / 8;
    const int gbU = (N_U + 127) / 128;
    const int gbI = (N_I + 127) / 128;

    // --- weight prep + count zeroing (1 launch) ---
    WprepArgs wp;
    wp.Wl[0] = W1l_iu; wp.Wr[0] = W1r_iu; wp.Lw[0] = L1W_u;
    wp.Wl[1] = W1l_ui; wp.Wr[1] = W1r_ui; wp.Lw[1] = L1W_i;
    wp.Wl[2] = W2l_iu; wp.Wr[2] = W2r_iu; wp.Lw[2] = L2W_u;
    wp.Wl[3] = W2l_ui; wp.Wr[3] = W2r_ui; wp.Lw[3] = L2W_i;
    wp.oh = w_h; wp.ol = w_l;
    wp.cnt_u = cnt_u; wp.cnt_i = cnt_i; wp.N_U = N_U; wp.N_I = N_I;
    k_wprep_all<<<256, 256>>>(wp);

    // --- CSR build ---
    k_count2<<<(2 * E + 255) / 256, 256>>>(iu_dst, cnt_u, ui_dst, cnt_i, E);
    k_scan1b<<<nbU + nbI, 256>>>(cnt_u, rp_u, bsum_u, N_U, nbU,
                                 cnt_i, rp_i, bsum_i, N_I);
    k_scan2b<<<1, 64>>>(bsum_u, nbU, bsum_i, nbI);
    k_scan3b<<<(N_U + N_I + 255) / 256, 256>>>(rp_u, bsum_u, cur_u, N_U,
                                               rp_i, bsum_i, cur_i, N_I, E);
    k_fill2<<<(2 * E + 255) / 256, 256>>>(iu_src, iu_dst, cur_u, eidx_u,
                                          ui_src, ui_dst, cur_i, eidx_i, E);

    GatherArgs gu1 = {x_item, rp_u, eidx_u, agg_u, N_U};
    GatherArgs gi1 = {x_user, rp_i, eidx_i, agg_i, N_I};
    GatherArgs gu2 = {h1_i, rp_u, eidx_u, agg_u, N_U};
    GatherArgs gi2 = {h1_u, rp_i, eidx_i, agg_i, N_I};
    GemmArgs mu1 = {agg_u, x_user, w_h + 0 * 16384, w_l + 0 * 16384,
                    b1_iu, L1b_u, h1_u, N_U};
    GemmArgs mi1 = {agg_i, x_item, w_h + 1 * 16384, w_l + 1 * 16384,
                    b1_ui, L1b_i, h1_i, N_I};
    GemmArgs mu2 = {agg_u, h1_u, w_h + 2 * 16384, w_l + 2 * 16384,
                    b2_iu, L2b_u, out_u, N_U};
    GemmArgs mi2 = {agg_i, h1_i, w_h + 3 * 16384, w_l + 3 * 16384,
                    b2_ui, L2b_i, out_i, N_I};

    // --- layer 1 ---
    k_gather2<<<gaU + gaI, 256>>>(gu1, gi1, gaU);
    k_gemm2<<<gbU + gbI, GT, SM_TOTAL2>>>(mu1, mi1, gbU, 1);
    // --- layer 2 ---
    k_gather2<<<gaU + gaI, 256>>>(gu2, gi2, gaU);
    k_gemm2<<<gbU + gbI, GT, SM_TOTAL2>>>(mu2, mi2, gbU, 0);
}